// round 6
// baseline (speedup 1.0000x reference)
#include <cuda_runtime.h>

#define NN 50000
#define EE 800000
#define NEG 0.2f

typedef unsigned long long u64;

// ---------------- scratch (static device globals; no allocation) ----------------
__device__ __align__(16) float    g_gl1[NN * 128];
__device__ __align__(16) float    g_gr1[NN * 128];
__device__ __align__(16) float    g_h1 [NN * 128];
__device__ __align__(16) float    g_gl2[NN * 32];
__device__ __align__(16) float    g_gr2[NN * 32];
// CSR by dst
__device__ unsigned g_cnt[NN];
__device__ unsigned g_rowstart[NN];
__device__ unsigned g_cursor[NN];
__device__ int      g_csrc[EE];

// ---------------- f32x2 helpers ----------------
__device__ __forceinline__ u64 pack2(float lo, float hi) {
    u64 r;
    asm("mov.b64 %0, {%1, %2};" : "=l"(r) : "f"(lo), "f"(hi));
    return r;
}
__device__ __forceinline__ float2 unpack2(u64 v) {
    float2 r;
    asm("mov.b64 {%0, %1}, %2;" : "=f"(r.x), "=f"(r.y) : "l"(v));
    return r;
}
__device__ __forceinline__ void ffma2(u64& d, u64 a, u64 b) {
    asm("fma.rn.f32x2 %0, %1, %2, %0;" : "+l"(d) : "l"(a), "l"(b));
}

// ---------------- CSR build ----------------
__global__ void csr_init_kernel() {
    int i = blockIdx.x * blockDim.x + threadIdx.x;
    if (i < NN) g_cnt[i] = 0u;
}
__global__ void csr_hist_kernel(const int* __restrict__ ei) {
    int i = blockIdx.x * blockDim.x + threadIdx.x;
    if (i < EE) atomicAdd(&g_cnt[ei[EE + i]], 1u);
}
__global__ __launch_bounds__(1024) void csr_scan_kernel() {
    __shared__ unsigned s[1024];
    const int T = 1024;
    const int CH = (NN + T - 1) / T;
    int t = threadIdx.x;
    int base = t * CH;
    unsigned sum = 0;
    for (int i = 0; i < CH; i++) {
        int j = base + i;
        if (j < NN) sum += g_cnt[j];
    }
    s[t] = sum;
    __syncthreads();
    for (int off = 1; off < T; off <<= 1) {
        unsigned u = (t >= off) ? s[t - off] : 0u;
        __syncthreads();
        s[t] += u;
        __syncthreads();
    }
    unsigned run = s[t] - sum;
    for (int i = 0; i < CH; i++) {
        int j = base + i;
        if (j < NN) {
            unsigned c = g_cnt[j];
            g_rowstart[j] = run;
            g_cursor[j]   = run;
            run += c;
        }
    }
}
__global__ void csr_fill_kernel(const int* __restrict__ ei) {
    int i = blockIdx.x * blockDim.x + threadIdx.x;
    if (i < EE) {
        int d = ei[EE + i];
        unsigned pos = atomicAdd(&g_cursor[d], 1u);
        g_csrc[pos] = ei[i];
    }
}

// ---------------- GEMM: W in smem, A streamed via LDG.128 (prefetch d1) ----------
// A:[n,128] row-major; W:[128,M]; blockIdx.y picks W1/W2. 256 threads.
// TXN=M/CT threads along N, TYN=256/TXN along rows, RT=RB/TYN rows/thread.
template <int M, int CT, int RB>
__global__ __launch_bounds__(256) void gemm_kernel(
    const float* __restrict__ A, int n,
    const float* __restrict__ W1, const float* __restrict__ b1, float* __restrict__ C1,
    const float* __restrict__ W2, const float* __restrict__ b2, float* __restrict__ C2)
{
    constexpr int K   = 128;
    constexpr int TXN = M / CT;
    constexpr int TYN = 256 / TXN;
    constexpr int RT  = RB / TYN;      // 4
    constexpr int CP  = CT / 2;        // 4 or 2

    extern __shared__ float sm[];
    float* Ws = sm;                    // K x M

    const float* __restrict__ W = blockIdx.y ? W2 : W1;
    const float* __restrict__ b = blockIdx.y ? b2 : b1;
    float* __restrict__       C = blockIdx.y ? C2 : C1;

    const int tid  = threadIdx.x;
    const int row0 = blockIdx.x * RB;

    for (int i = tid; i < K * M / 4; i += 256) {
        reinterpret_cast<float4*>(Ws)[i] = reinterpret_cast<const float4*>(W)[i];
    }
    __syncthreads();

    const int tx = tid % TXN;
    const int ty = tid / TXN;

    // row indices for this thread (clamped for loads; stores guarded)
    int rows[RT];
#pragma unroll
    for (int i = 0; i < RT; i++) {
        int r = row0 + ty * RT + i;
        rows[i] = (r < n) ? r : (n - 1);
    }
    const float4* __restrict__ A4 = reinterpret_cast<const float4*>(A);

    u64 acc[RT][CP];
    const u64 zz = pack2(0.f, 0.f);
#pragma unroll
    for (int i = 0; i < RT; i++)
#pragma unroll
        for (int j = 0; j < CP; j++) acc[i][j] = zz;

    // prefetch k4 = 0
    float4 avn[RT];
#pragma unroll
    for (int i = 0; i < RT; i++) avn[i] = __ldg(&A4[rows[i] * 32]);

    for (int k4 = 0; k4 < K / 4; ++k4) {
        float4 av[RT];
#pragma unroll
        for (int i = 0; i < RT; i++) av[i] = avn[i];
        if (k4 + 1 < K / 4) {
#pragma unroll
            for (int i = 0; i < RT; i++)
                avn[i] = __ldg(&A4[rows[i] * 32 + k4 + 1]);
        }
#pragma unroll
        for (int kk = 0; kk < 4; ++kk) {
            u64 wv[CP];
            const float* wrow = Ws + (k4 * 4 + kk) * M + tx * CT;
#pragma unroll
            for (int j2 = 0; j2 < CP / 2; ++j2) {
                ulonglong2 u = reinterpret_cast<const ulonglong2*>(wrow)[j2];
                wv[j2 * 2]     = u.x;
                wv[j2 * 2 + 1] = u.y;
            }
            if constexpr (CP % 2) {
                wv[CP - 1] = reinterpret_cast<const u64*>(wrow)[CP - 1];
            }
#pragma unroll
            for (int i = 0; i < RT; i++) {
                float a = (kk == 0) ? av[i].x : (kk == 1) ? av[i].y
                        : (kk == 2) ? av[i].z : av[i].w;
                u64 ap = pack2(a, a);
#pragma unroll
                for (int j = 0; j < CP; j++) ffma2(acc[i][j], ap, wv[j]);
            }
        }
    }

#pragma unroll
    for (int i = 0; i < RT; i++) {
        int r = row0 + ty * RT + i;
        if (r < n) {
#pragma unroll
            for (int j = 0; j < CP; j++) {
                int c = tx * CT + j * 2;
                float2 v = unpack2(acc[i][j]);
                C[r * M + c]     = v.x + b[c];
                C[r * M + c + 1] = v.y + b[c + 1];
            }
        }
    }
}

// ---------------- layer 1: fused attention aggregation (warp per dst) ----------------
__global__ __launch_bounds__(256) void agg1_kernel(const float* __restrict__ att,
                                                   const float* __restrict__ bias) {
    const int lane = threadIdx.x & 31;
    const int d = blockIdx.x * (blockDim.x >> 5) + (threadIdx.x >> 5);
    if (d >= NN) return;

    const float4* __restrict__ gl4 = reinterpret_cast<const float4*>(g_gl1);
    const float4  grd = reinterpret_cast<const float4*>(g_gr1)[d * 32 + lane];
    const float4  at  = reinterpret_cast<const float4*>(att)[lane];

    float4 acc = make_float4(0.f, 0.f, 0.f, 0.f);
    float  den = 0.f;

    const unsigned start = g_rowstart[d];
    const unsigned deg   = g_cnt[d];

    int s1 = (deg > 0) ? g_csrc[start]     : d;
    int s2 = (deg > 1) ? g_csrc[start + 1] : d;
    float4 gcur  = gl4[d  * 32 + lane];
    float4 gnext = gl4[s1 * 32 + lane];

    for (unsigned j = 0; j <= deg; ++j) {
        float4 gnn = gl4[s2 * 32 + lane];
        s2 = (j + 3 <= deg) ? g_csrc[start + j + 2] : d;

        float m0 = gcur.x + grd.x; m0 = (m0 > 0.f) ? m0 : NEG * m0;
        float m1 = gcur.y + grd.y; m1 = (m1 > 0.f) ? m1 : NEG * m1;
        float m2 = gcur.z + grd.z; m2 = (m2 > 0.f) ? m2 : NEG * m2;
        float m3 = gcur.w + grd.w; m3 = (m3 > 0.f) ? m3 : NEG * m3;
        float p = at.x * m0 + at.y * m1 + at.z * m2 + at.w * m3;
        p += __shfl_xor_sync(0xffffffffu, p, 1);
        p += __shfl_xor_sync(0xffffffffu, p, 2);
        p += __shfl_xor_sync(0xffffffffu, p, 4);
        float w = __expf(p);
        acc.x += w * gcur.x;
        acc.y += w * gcur.y;
        acc.z += w * gcur.z;
        acc.w += w * gcur.w;
        den += w;

        gcur = gnext;
        gnext = gnn;
    }

    const float inv = 1.f / den;
    const float4 b = reinterpret_cast<const float4*>(bias)[lane];
    float v0 = acc.x * inv + b.x; v0 = (v0 > 0.f) ? v0 : expm1f(v0);
    float v1 = acc.y * inv + b.y; v1 = (v1 > 0.f) ? v1 : expm1f(v1);
    float v2 = acc.z * inv + b.z; v2 = (v2 > 0.f) ? v2 : expm1f(v2);
    float v3 = acc.w * inv + b.w; v3 = (v3 > 0.f) ? v3 : expm1f(v3);
    reinterpret_cast<float4*>(g_h1)[d * 32 + lane] = make_float4(v0, v1, v2, v3);
}

// ---------------- layer 2: aggregation, 4 dsts per warp (8 lanes / dst) -------------
__global__ __launch_bounds__(256) void agg2_kernel(const float* __restrict__ att,
                                                   const float* __restrict__ bias,
                                                   float* __restrict__ out) {
    const int lane = threadIdx.x & 31;
    const int grp  = lane >> 3;
    const int lg   = lane & 7;
    const int wid  = blockIdx.x * (blockDim.x >> 5) + (threadIdx.x >> 5);
    int d = wid * 4 + grp;
    const bool dvalid = (d < NN);
    if (d >= NN) d = NN - 1;

    const float4* __restrict__ gl4 = reinterpret_cast<const float4*>(g_gl2);
    const float4 grd  = reinterpret_cast<const float4*>(g_gr2)[d * 8 + lg];
    const float4 at   = reinterpret_cast<const float4*>(att)[lg];

    const unsigned start = g_rowstart[d];
    const unsigned deg   = dvalid ? g_cnt[d] : 0u;

    unsigned mdeg = deg;
#pragma unroll
    for (int off = 8; off < 32; off <<= 1) {
        unsigned o = __shfl_xor_sync(0xffffffffu, mdeg, off);
        mdeg = (o > mdeg) ? o : mdeg;
    }

    float4 acc = make_float4(0.f, 0.f, 0.f, 0.f);
    float  den = 0.f;

    int snext = (deg > 0) ? g_csrc[start] : d;
    float4 g = gl4[d * 8 + lg];

    for (unsigned j = 0; j <= mdeg; ++j) {
        float4 gc = g;
        int snn = (j + 2 <= deg) ? g_csrc[start + j + 1] : d;
        g = gl4[snext * 8 + lg];
        snext = snn;

        float m0 = gc.x + grd.x; m0 = (m0 > 0.f) ? m0 : NEG * m0;
        float m1 = gc.y + grd.y; m1 = (m1 > 0.f) ? m1 : NEG * m1;
        float m2 = gc.z + grd.z; m2 = (m2 > 0.f) ? m2 : NEG * m2;
        float m3 = gc.w + grd.w; m3 = (m3 > 0.f) ? m3 : NEG * m3;
        float p = at.x * m0 + at.y * m1 + at.z * m2 + at.w * m3;
        p += __shfl_xor_sync(0xffffffffu, p, 1);
        p += __shfl_xor_sync(0xffffffffu, p, 2);
        p += __shfl_xor_sync(0xffffffffu, p, 4);
        float w = (j <= deg) ? __expf(p) : 0.f;
        acc.x += w * gc.x;
        acc.y += w * gc.y;
        acc.z += w * gc.z;
        acc.w += w * gc.w;
        den += w;
    }

    if (dvalid) {
        const float inv = 1.f / den;
        const float4 b = reinterpret_cast<const float4*>(bias)[lg];
        reinterpret_cast<float4*>(out)[d * 8 + lg] =
            make_float4(acc.x * inv + b.x, acc.y * inv + b.y,
                        acc.z * inv + b.z, acc.w * inv + b.w);
    }
}

// ---------------- launch ----------------
extern "C" void kernel_launch(void* const* d_in, const int* in_sizes, int n_in,
                              void* d_out, int out_size) {
    const float* x    = (const float*)d_in[0];
    const int*   ei   = (const int*)d_in[1];
    const float* Wl1  = (const float*)d_in[2];
    const float* bl1  = (const float*)d_in[3];
    const float* Wr1  = (const float*)d_in[4];
    const float* br1  = (const float*)d_in[5];
    const float* att1 = (const float*)d_in[6];
    const float* bias1= (const float*)d_in[7];
    const float* Wl2  = (const float*)d_in[8];
    const float* bl2  = (const float*)d_in[9];
    const float* Wr2  = (const float*)d_in[10];
    const float* br2  = (const float*)d_in[11];
    const float* att2 = (const float*)d_in[12];
    const float* bias2= (const float*)d_in[13];
    float* out = (float*)d_out;

    // gemm1: M=128, CT=8, RB=64  -> smem 128*128*4 = 65536
    // gemm2: M=32,  CT=4, RB=128 -> smem 128*32*4  = 16384
    cudaFuncSetAttribute((gemm_kernel<128, 8, 64>),
                         cudaFuncAttributeMaxDynamicSharedMemorySize, 65536);
    cudaFuncSetAttribute((gemm_kernel<32, 4, 128>),
                         cudaFuncAttributeMaxDynamicSharedMemorySize, 16384);

    float *gl1p, *gr1p, *h1p, *gl2p, *gr2p;
    cudaGetSymbolAddress((void**)&gl1p, g_gl1);
    cudaGetSymbolAddress((void**)&gr1p, g_gr1);
    cudaGetSymbolAddress((void**)&h1p,  g_h1);
    cudaGetSymbolAddress((void**)&gl2p, g_gl2);
    cudaGetSymbolAddress((void**)&gr2p, g_gr2);

    // slots 1-3: CSR prefix; slot 4: gemm1 (profiled by ncu)
    csr_init_kernel<<<(NN + 255) / 256, 256>>>();
    csr_hist_kernel<<<(EE + 255) / 256, 256>>>(ei);
    csr_scan_kernel<<<1, 1024>>>();
    gemm_kernel<128, 8, 64><<<dim3((NN + 63) / 64, 2), 256, 65536>>>(
        x, NN, Wl1, bl1, gl1p, Wr1, br1, gr1p);
    csr_fill_kernel<<<(EE + 255) / 256, 256>>>(ei);

    agg1_kernel<<<(NN + 7) / 8, 256>>>(att1, bias1);

    gemm_kernel<32, 4, 128><<<dim3((NN + 127) / 128, 2), 256, 16384>>>(
        h1p, NN, Wl2, bl2, gl2p, Wr2, br2, gr2p);
    agg2_kernel<<<(NN + 31) / 32, 256>>>(att2, bias2, out);
}

// round 7
// speedup vs baseline: 1.0853x; 1.0853x over previous
#include <cuda_runtime.h>

#define NN 50000
#define EE 800000
#define NEG 0.2f

typedef unsigned long long u64;

// ---------------- scratch (static device globals; no allocation) ----------------
__device__ __align__(16) float    g_gl1[NN * 128];
__device__ __align__(16) float    g_gr1[NN * 128];
__device__ __align__(16) float    g_h1 [NN * 128];
__device__ __align__(16) float    g_gl2[NN * 32];
__device__ __align__(16) float    g_gr2[NN * 32];
// CSR by dst
__device__ unsigned g_cnt[NN];
__device__ unsigned g_rowstart[NN];
__device__ unsigned g_cursor[NN];
__device__ int      g_csrc[EE];

// ---------------- f32x2 helpers ----------------
__device__ __forceinline__ u64 pack2(float lo, float hi) {
    u64 r;
    asm("mov.b64 %0, {%1, %2};" : "=l"(r) : "f"(lo), "f"(hi));
    return r;
}
__device__ __forceinline__ float2 unpack2(u64 v) {
    float2 r;
    asm("mov.b64 {%0, %1}, %2;" : "=f"(r.x), "=f"(r.y) : "l"(v));
    return r;
}
__device__ __forceinline__ void ffma2(u64& d, u64 a, u64 b) {
    asm("fma.rn.f32x2 %0, %1, %2, %0;" : "+l"(d) : "l"(a), "l"(b));
}

// ---------------- CSR build ----------------
__global__ void csr_init_kernel() {
    int i = blockIdx.x * blockDim.x + threadIdx.x;
    if (i < NN) g_cnt[i] = 0u;
}
__global__ void csr_hist_kernel(const int* __restrict__ ei) {
    int i = blockIdx.x * blockDim.x + threadIdx.x;
    if (i < EE) atomicAdd(&g_cnt[ei[EE + i]], 1u);
}
__global__ __launch_bounds__(1024) void csr_scan_kernel() {
    __shared__ unsigned s[1024];
    const int T = 1024;
    const int CH = (NN + T - 1) / T;
    int t = threadIdx.x;
    int base = t * CH;
    unsigned sum = 0;
    for (int i = 0; i < CH; i++) {
        int j = base + i;
        if (j < NN) sum += g_cnt[j];
    }
    s[t] = sum;
    __syncthreads();
    for (int off = 1; off < T; off <<= 1) {
        unsigned u = (t >= off) ? s[t - off] : 0u;
        __syncthreads();
        s[t] += u;
        __syncthreads();
    }
    unsigned run = s[t] - sum;
    for (int i = 0; i < CH; i++) {
        int j = base + i;
        if (j < NN) {
            unsigned c = g_cnt[j];
            g_rowstart[j] = run;
            g_cursor[j]   = run;
            run += c;
        }
    }
}
__global__ void csr_fill_kernel(const int* __restrict__ ei) {
    int i = blockIdx.x * blockDim.x + threadIdx.x;
    if (i < EE) {
        int d = ei[EE + i];
        unsigned pos = atomicAdd(&g_cursor[d], 1u);
        g_csrc[pos] = ei[i];
    }
}

// ---------------- GEMM: conflict-free smem, f32x2, N-split for occupancy ----------
// A:[n,128] row-major; W:[128,M]. Block computes RB rows x MBLK cols of one matrix.
// grid.y = mat * (M/MBLK) + half. 256 threads; TXN=MBLK/CT; TYN=256/TXN; RT=RB/TYN.
// A smem: pitch 33 float4 (bank-offset 16B/row), rows assigned strided (ty + i*TYN).
// W smem: chunk-swizzled [k][chunk][tx] so each LDS.128 is 128B-contiguous per warp.
template <int M, int MBLK, int CT, int RB>
__global__ __launch_bounds__(256) void gemm_kernel(
    const float* __restrict__ A, int n,
    const float* __restrict__ W1, const float* __restrict__ b1, float* __restrict__ C1,
    const float* __restrict__ W2, const float* __restrict__ b2, float* __restrict__ C2)
{
    constexpr int K    = 128;
    constexpr int TXN  = MBLK / CT;     // 8
    constexpr int TYN  = 256 / TXN;     // 32
    constexpr int RT   = RB / TYN;      // 4
    constexpr int CP   = CT / 2;        // u64 accs per row: 4 or 2
    constexpr int NCH  = CT / 4;        // 16B chunks per thread: 2 or 1
    constexpr int NH   = M / MBLK;      // halves per matrix
    constexpr int AP   = 33;            // A pitch in float4

    extern __shared__ float sm[];
    float4* As4 = reinterpret_cast<float4*>(sm);        // RB * AP float4
    float4* Ws4 = reinterpret_cast<float4*>(sm) + RB * AP;  // K * MBLK/4 swizzled

    const int mat  = blockIdx.y / NH;
    const int col0 = (blockIdx.y % NH) * MBLK;
    const float* __restrict__ W = mat ? W2 : W1;
    const float* __restrict__ b = mat ? b2 : b1;
    float* __restrict__       C = mat ? C2 : C1;

    const int tid  = threadIdx.x;
    const int row0 = blockIdx.x * RB;

    // fill A tile: coalesced read, padded-pitch write
    for (int i = tid; i < RB * 32; i += 256) {
        int r  = i >> 5;
        int c4 = i & 31;
        int gr_ = row0 + r;
        float4 v = make_float4(0.f, 0.f, 0.f, 0.f);
        if (gr_ < n) v = reinterpret_cast<const float4*>(A)[gr_ * 32 + c4];
        As4[r * AP + c4] = v;
    }
    // fill W tile swizzled: src (k, c) -> dst (k*NCH + chunk)*TXN + txg
    for (int i = tid; i < K * (MBLK / 4); i += 256) {
        int k  = i / (MBLK / 4);
        int c4 = i % (MBLK / 4);
        int c  = c4 * 4;
        int txg   = c / CT;
        int chunk = (c % CT) >> 2;
        float4 v = reinterpret_cast<const float4*>(W + k * M + col0)[c4];
        Ws4[(k * NCH + chunk) * TXN + txg] = v;
    }
    __syncthreads();

    const int tx = tid % TXN;
    const int ty = tid / TXN;

    u64 acc[RT][CP];
    const u64 zz = pack2(0.f, 0.f);
#pragma unroll
    for (int i = 0; i < RT; i++)
#pragma unroll
        for (int j = 0; j < CP; j++) acc[i][j] = zz;

    for (int k4 = 0; k4 < K / 4; ++k4) {
        float4 av[RT];
#pragma unroll
        for (int i = 0; i < RT; i++)
            av[i] = As4[(ty + i * TYN) * AP + k4];   // strided rows: 1 wavefront

#pragma unroll
        for (int kk = 0; kk < 4; ++kk) {
            u64 wv[CP];
            const ulonglong2* wp = reinterpret_cast<const ulonglong2*>(
                Ws4 + (k4 * 4 + kk) * NCH * TXN);
#pragma unroll
            for (int jc = 0; jc < NCH; ++jc) {
                ulonglong2 u = wp[jc * TXN + tx];    // 128B contiguous per warp
                wv[jc * 2] = u.x;
                if constexpr (CP > 1) wv[jc * 2 + 1] = u.y;
            }
#pragma unroll
            for (int i = 0; i < RT; i++) {
                float a = (kk == 0) ? av[i].x : (kk == 1) ? av[i].y
                        : (kk == 2) ? av[i].z : av[i].w;
                u64 ap = pack2(a, a);
#pragma unroll
                for (int j = 0; j < CP; j++) ffma2(acc[i][j], ap, wv[j]);
            }
        }
    }

#pragma unroll
    for (int i = 0; i < RT; i++) {
        int r = row0 + ty + i * TYN;
        if (r < n) {
#pragma unroll
            for (int j = 0; j < CP; j++) {
                int c = col0 + tx * CT + j * 2;
                float2 v = unpack2(acc[i][j]);
                C[r * M + c]     = v.x + b[c];
                C[r * M + c + 1] = v.y + b[c + 1];
            }
        }
    }
}

// ---------------- layer 1: fused attention aggregation (warp per dst) ----------------
__global__ __launch_bounds__(256) void agg1_kernel(const float* __restrict__ att,
                                                   const float* __restrict__ bias) {
    const int lane = threadIdx.x & 31;
    const int d = blockIdx.x * (blockDim.x >> 5) + (threadIdx.x >> 5);
    if (d >= NN) return;

    const float4* __restrict__ gl4 = reinterpret_cast<const float4*>(g_gl1);
    const float4  grd = reinterpret_cast<const float4*>(g_gr1)[d * 32 + lane];
    const float4  at  = reinterpret_cast<const float4*>(att)[lane];

    float4 acc = make_float4(0.f, 0.f, 0.f, 0.f);
    float  den = 0.f;

    const unsigned start = g_rowstart[d];
    const unsigned deg   = g_cnt[d];

    int s1 = (deg > 0) ? g_csrc[start]     : d;
    int s2 = (deg > 1) ? g_csrc[start + 1] : d;
    float4 gcur  = gl4[d  * 32 + lane];
    float4 gnext = gl4[s1 * 32 + lane];

    for (unsigned j = 0; j <= deg; ++j) {
        float4 gnn = gl4[s2 * 32 + lane];
        s2 = (j + 3 <= deg) ? g_csrc[start + j + 2] : d;

        float m0 = gcur.x + grd.x; m0 = (m0 > 0.f) ? m0 : NEG * m0;
        float m1 = gcur.y + grd.y; m1 = (m1 > 0.f) ? m1 : NEG * m1;
        float m2 = gcur.z + grd.z; m2 = (m2 > 0.f) ? m2 : NEG * m2;
        float m3 = gcur.w + grd.w; m3 = (m3 > 0.f) ? m3 : NEG * m3;
        float p = at.x * m0 + at.y * m1 + at.z * m2 + at.w * m3;
        p += __shfl_xor_sync(0xffffffffu, p, 1);
        p += __shfl_xor_sync(0xffffffffu, p, 2);
        p += __shfl_xor_sync(0xffffffffu, p, 4);
        float w = __expf(p);
        acc.x += w * gcur.x;
        acc.y += w * gcur.y;
        acc.z += w * gcur.z;
        acc.w += w * gcur.w;
        den += w;

        gcur = gnext;
        gnext = gnn;
    }

    const float inv = 1.f / den;
    const float4 b = reinterpret_cast<const float4*>(bias)[lane];
    float v0 = acc.x * inv + b.x; v0 = (v0 > 0.f) ? v0 : expm1f(v0);
    float v1 = acc.y * inv + b.y; v1 = (v1 > 0.f) ? v1 : expm1f(v1);
    float v2 = acc.z * inv + b.z; v2 = (v2 > 0.f) ? v2 : expm1f(v2);
    float v3 = acc.w * inv + b.w; v3 = (v3 > 0.f) ? v3 : expm1f(v3);
    reinterpret_cast<float4*>(g_h1)[d * 32 + lane] = make_float4(v0, v1, v2, v3);
}

// ---------------- layer 2: aggregation, 4 dsts per warp (8 lanes / dst) -------------
__global__ __launch_bounds__(256) void agg2_kernel(const float* __restrict__ att,
                                                   const float* __restrict__ bias,
                                                   float* __restrict__ out) {
    const int lane = threadIdx.x & 31;
    const int grp  = lane >> 3;
    const int lg   = lane & 7;
    const int wid  = blockIdx.x * (blockDim.x >> 5) + (threadIdx.x >> 5);
    int d = wid * 4 + grp;
    const bool dvalid = (d < NN);
    if (d >= NN) d = NN - 1;

    const float4* __restrict__ gl4 = reinterpret_cast<const float4*>(g_gl2);
    const float4 grd  = reinterpret_cast<const float4*>(g_gr2)[d * 8 + lg];
    const float4 at   = reinterpret_cast<const float4*>(att)[lg];

    const unsigned start = g_rowstart[d];
    const unsigned deg   = dvalid ? g_cnt[d] : 0u;

    unsigned mdeg = deg;
#pragma unroll
    for (int off = 8; off < 32; off <<= 1) {
        unsigned o = __shfl_xor_sync(0xffffffffu, mdeg, off);
        mdeg = (o > mdeg) ? o : mdeg;
    }

    float4 acc = make_float4(0.f, 0.f, 0.f, 0.f);
    float  den = 0.f;

    int snext = (deg > 0) ? g_csrc[start] : d;
    float4 g = gl4[d * 8 + lg];

    for (unsigned j = 0; j <= mdeg; ++j) {
        float4 gc = g;
        int snn = (j + 2 <= deg) ? g_csrc[start + j + 1] : d;
        g = gl4[snext * 8 + lg];
        snext = snn;

        float m0 = gc.x + grd.x; m0 = (m0 > 0.f) ? m0 : NEG * m0;
        float m1 = gc.y + grd.y; m1 = (m1 > 0.f) ? m1 : NEG * m1;
        float m2 = gc.z + grd.z; m2 = (m2 > 0.f) ? m2 : NEG * m2;
        float m3 = gc.w + grd.w; m3 = (m3 > 0.f) ? m3 : NEG * m3;
        float p = at.x * m0 + at.y * m1 + at.z * m2 + at.w * m3;
        p += __shfl_xor_sync(0xffffffffu, p, 1);
        p += __shfl_xor_sync(0xffffffffu, p, 2);
        p += __shfl_xor_sync(0xffffffffu, p, 4);
        float w = (j <= deg) ? __expf(p) : 0.f;
        acc.x += w * gc.x;
        acc.y += w * gc.y;
        acc.z += w * gc.z;
        acc.w += w * gc.w;
        den += w;
    }

    if (dvalid) {
        const float inv = 1.f / den;
        const float4 b = reinterpret_cast<const float4*>(bias)[lg];
        reinterpret_cast<float4*>(out)[d * 8 + lg] =
            make_float4(acc.x * inv + b.x, acc.y * inv + b.y,
                        acc.z * inv + b.z, acc.w * inv + b.w);
    }
}

// ---------------- launch ----------------
extern "C" void kernel_launch(void* const* d_in, const int* in_sizes, int n_in,
                              void* d_out, int out_size) {
    const float* x    = (const float*)d_in[0];
    const int*   ei   = (const int*)d_in[1];
    const float* Wl1  = (const float*)d_in[2];
    const float* bl1  = (const float*)d_in[3];
    const float* Wr1  = (const float*)d_in[4];
    const float* br1  = (const float*)d_in[5];
    const float* att1 = (const float*)d_in[6];
    const float* bias1= (const float*)d_in[7];
    const float* Wl2  = (const float*)d_in[8];
    const float* bl2  = (const float*)d_in[9];
    const float* Wr2  = (const float*)d_in[10];
    const float* br2  = (const float*)d_in[11];
    const float* att2 = (const float*)d_in[12];
    const float* bias2= (const float*)d_in[13];
    float* out = (float*)d_out;

    // gemm1: M=128, MBLK=64, CT=8, RB=128 -> smem 128*33*16 + 128*64*4 = 100352
    // gemm2: M=32,  MBLK=32, CT=4, RB=128 -> smem 128*33*16 + 128*32*4 = 83968
    const int smem1 = 128 * 33 * 16 + 128 * 64 * 4;
    const int smem2 = 128 * 33 * 16 + 128 * 32 * 4;
    cudaFuncSetAttribute((gemm_kernel<128, 64, 8, 128>),
                         cudaFuncAttributeMaxDynamicSharedMemorySize, smem1);
    cudaFuncSetAttribute((gemm_kernel<32, 32, 4, 128>),
                         cudaFuncAttributeMaxDynamicSharedMemorySize, smem2);

    float *gl1p, *gr1p, *h1p, *gl2p, *gr2p;
    cudaGetSymbolAddress((void**)&gl1p, g_gl1);
    cudaGetSymbolAddress((void**)&gr1p, g_gr1);
    cudaGetSymbolAddress((void**)&h1p,  g_h1);
    cudaGetSymbolAddress((void**)&gl2p, g_gl2);
    cudaGetSymbolAddress((void**)&gr2p, g_gr2);

    // slots 1-3: CSR prefix; slot 4: gemm1 (profiled by ncu)
    csr_init_kernel<<<(NN + 255) / 256, 256>>>();
    csr_hist_kernel<<<(EE + 255) / 256, 256>>>(ei);
    csr_scan_kernel<<<1, 1024>>>();
    gemm_kernel<128, 64, 8, 128><<<dim3((NN + 127) / 128, 4), 256, smem1>>>(
        x, NN, Wl1, bl1, gl1p, Wr1, br1, gr1p);
    csr_fill_kernel<<<(EE + 255) / 256, 256>>>(ei);

    agg1_kernel<<<(NN + 7) / 8, 256>>>(att1, bias1);

    gemm_kernel<32, 32, 4, 128><<<dim3((NN + 127) / 128, 2), 256, smem2>>>(
        h1p, NN, Wl2, bl2, gl2p, Wr2, br2, gr2p);
    agg2_kernel<<<(NN + 31) / 32, 256>>>(att2, bias2, out);
}